// round 9
// baseline (speedup 1.0000x reference)
#include <cuda_runtime.h>
#include <cuda_bf16.h>
#include <cstdint>

#define GG   8
#define KK   1024
#define DD   64
#define BB   16
#define TS   4000
#define CF   512
#define TT   128        // tokens per CTA
#define NC   64         // codes per chunk
#define NCH  16
#define NTH  128
#define PTH  256

// ---------------- device globals ----------------
__device__ float g_e2[GG * KK];
__device__ unsigned int g_e2max[GG];
__device__ __align__(16) __nv_bfloat16 g_cbh[GG * KK * DD];
__device__ __align__(16) __nv_bfloat16 g_cbl[GG * KK * DD];

// ---------------- smem layout (bytes) ----------------
#define OFF_AH    0        // 16384: A hi bf16 SW128 (128 rows x 128B)
#define OFF_B     16384    // 32768: x stage / 2 B bufs (each: hi 8K + lo 8K) / gather stage
#define OFF_E2S   49152    // 4096
#define OFF_X2S   53248    // 512  (x2 per token, exact fp32)
#define OFF_XL2   53760    // 512  (||x - xh||^2 per token)
#define OFF_BIX   54272    // 512
#define OFF_P1V   54784    // 1024: [2][128] min1 (reused as fallback x scratch)
#define OFF_P1I   55808    // 1024
#define OFF_P2V   56832    // 1024
#define OFF_FLG   57856    // 520
#define SMEM_BYTES 58376

#define SW128(o) ((o) ^ (((o) >> 3) & 0x70))

__device__ __forceinline__ uint32_t smem_u32(const void* p) {
    uint32_t a;
    asm("{ .reg .u64 t; cvta.to.shared.u64 t, %1; cvt.u32.u64 %0, t; }" : "=r"(a) : "l"(p));
    return a;
}

#define LDMX4(r0, r1, r2, r3, a) \
    asm volatile("ldmatrix.sync.aligned.m8n8.x4.shared.b16 {%0,%1,%2,%3}, [%4];" \
        : "=r"(r0), "=r"(r1), "=r"(r2), "=r"(r3) : "r"(a))

#define MMA16816(c0, c1, c2, c3, a0, a1, a2, a3, b0, b1) \
    asm volatile("mma.sync.aligned.m16n8k16.row.col.f32.bf16.bf16.f32 " \
        "{%0,%1,%2,%3}, {%4,%5,%6,%7}, {%8,%9}, {%0,%1,%2,%3};" \
        : "+f"(c0), "+f"(c1), "+f"(c2), "+f"(c3) \
        : "r"(a0), "r"(a1), "r"(a2), "r"(a3), "r"(b0), "r"(b1))

#define CP_ASYNC16(dst, src) \
    asm volatile("cp.async.cg.shared.global [%0], [%1], 16;" :: "r"(dst), "l"(src) : "memory")
#define CP_COMMIT  asm volatile("cp.async.commit_group;" ::: "memory")
#define CP_WAIT(n) asm volatile("cp.async.wait_group %0;" :: "n"(n) : "memory")

// ---------------- prep: bf16 split codebook + e2 + e2max ----------------
__global__ void prep_kernel(const float* __restrict__ cb) {
    int r = blockIdx.x * blockDim.x + threadIdx.x;
    if (r < GG * KK) {
        const float* row = cb + (size_t)r * DD;
        float s = 0.f;
        #pragma unroll
        for (int d = 0; d < DD; ++d) {
            float v = row[d];
            s = fmaf(v, v, s);
            __nv_bfloat16 h = __float2bfloat16(v);
            g_cbh[(size_t)r * DD + d] = h;
            g_cbl[(size_t)r * DD + d] = __float2bfloat16(v - __bfloat162float(h));
        }
        g_e2[r] = s;
        atomicMax(&g_e2max[r / KK], __float_as_uint(s));
    }
}

__global__ __launch_bounds__(NTH, 3)
void vq_main(const float* __restrict__ x, const float* __restrict__ cbf,
             float* __restrict__ out, int two_copies) {
    extern __shared__ char smem[];
    const uint32_t base = smem_u32(smem);
    float* stg  = (float*)(smem + OFF_B);
    float* e2s  = (float*)(smem + OFF_E2S);
    float* x2s  = (float*)(smem + OFF_X2S);
    float* xl2s = (float*)(smem + OFF_XL2);
    int*   bix  = (int*)  (smem + OFF_BIX);
    float* p1v  = (float*)(smem + OFF_P1V);
    int*   p1i  = (int*)  (smem + OFF_P1I);
    float* p2v  = (float*)(smem + OFF_P2V);
    int*   flg  = (int*)  (smem + OFF_FLG);

    const int tid = threadIdx.x;
    const int wid = tid >> 5;
    const int lane = tid & 31;

    const int tile = blockIdx.x & 31;
    const int b = (blockIdx.x >> 5) & 15;
    const int g = blockIdx.x >> 9;
    const int t0 = tile * TT;
    const int nt = min(TT, TS - t0);

    if (tid == 0) flg[0] = 0;

    // ---- stage x tile fp32 into the B region ([d][t], zero-padded) ----
    const float* xb = x + ((size_t)(b * CF + g * DD)) * TS + t0;
    if (nt == TT) {
        #pragma unroll
        for (int i = tid; i < DD * (TT / 4); i += NTH) {
            int dd = i >> 5, tq = i & 31;
            float4 v = *(const float4*)(xb + (size_t)dd * TS + tq * 4);
            *(float4*)&stg[dd * TT + tq * 4] = v;
        }
    } else {
        for (int i = tid; i < DD * TT; i += NTH) {
            int dd = i / TT, tt = i % TT;
            stg[dd * TT + tt] = (tt < nt) ? xb[(size_t)dd * TS + tt] : 0.f;
        }
    }
    for (int i = tid; i < KK; i += NTH) e2s[i] = g_e2[g * KK + i];
    __syncthreads();

    // ---- build A hi (SW128 rows of 128B) + x2 + xl2; thread t = token t ----
    {
        float s = 0.f, sl = 0.f;
        #pragma unroll
        for (int q = 0; q < 8; ++q) {
            uint32_t hp[4];
            #pragma unroll
            for (int pr = 0; pr < 4; ++pr) {
                float v0 = stg[(q * 8 + pr * 2) * TT + tid];
                float v1 = stg[(q * 8 + pr * 2 + 1) * TT + tid];
                s = fmaf(v0, v0, s);
                s = fmaf(v1, v1, s);
                __nv_bfloat16 h0 = __float2bfloat16(v0), h1 = __float2bfloat16(v1);
                float l0 = v0 - __bfloat162float(h0);
                float l1 = v1 - __bfloat162float(h1);
                sl = fmaf(l0, l0, sl);
                sl = fmaf(l1, l1, sl);
                hp[pr] = ((uint32_t)__bfloat16_as_ushort(h1) << 16) | __bfloat16_as_ushort(h0);
            }
            uint32_t off = SW128((uint32_t)(tid * 128 + q * 16));
            asm volatile("st.shared.v4.b32 [%0], {%1,%2,%3,%4};"
                :: "r"(base + OFF_AH + off), "r"(hp[0]), "r"(hp[1]), "r"(hp[2]), "r"(hp[3]) : "memory");
        }
        x2s[tid] = s;
        xl2s[tid] = sl;
    }
    __syncthreads();   // A built; B region free

    // ---- warp tiling: 64 tokens x 32 codes per warp ----
    const int m0 = (wid >> 1) * 64;
    const int n0 = (wid & 1) * 32;
    const int half = wid & 1;
    const int gq = lane >> 2;
    const int t4 = lane & 3;

    const uint32_t aRow = (uint32_t)(m0 + (lane & 15));
    const uint32_t aCs = (uint32_t)(lane >> 4);
    const uint32_t bRowBase = (uint32_t)(n0 + (lane & 7) + ((lane >> 4) << 3));
    const uint32_t bCs = (uint32_t)((lane >> 3) & 1);

    uint32_t aB[4], aS[4];
    #pragma unroll
    for (int mt = 0; mt < 4; ++mt) {
        uint32_t r = aRow + 16u * mt;
        aB[mt] = base + OFF_AH + r * 128u;
        aS[mt] = r & 7u;
    }
    uint32_t bRo[2], bSh[2];
    #pragma unroll
    for (int np = 0; np < 2; ++np) {
        uint32_t r = bRowBase + 16u * np;
        bRo[np] = r * 128u;
        bSh[np] = r & 7u;
    }

    const float INF = __int_as_float(0x7f800000);
    float m1[8], m2[8];
    int i1[8];
    #pragma unroll
    for (int r = 0; r < 8; ++r) { m1[r] = INF; m2[r] = INF; i1[r] = 0; }

    const char* cbh = (const char*)(g_cbh + (size_t)g * KK * DD);
    const char* cbl = (const char*)(g_cbl + (size_t)g * KK * DD);

    // prefetch chunk 0 (hi at +0, lo at +8192 within 16K buffer)
    {
        #pragma unroll
        for (int i = tid; i < 1024; i += NTH) {
            int hf = i >> 9, idx = i & 511;
            const char* s = (hf ? cbl : cbh) + (size_t)idx * 16;
            uint32_t d = base + OFF_B + (uint32_t)hf * 8192u + SW128((uint32_t)(idx * 16));
            CP_ASYNC16(d, s);
        }
        CP_COMMIT;
    }

    for (int c = 0; c < NCH; ++c) {
        __syncthreads();
        if (c + 1 < NCH) {
            const char* srcH = cbh + (size_t)(c + 1) * NC * DD * 2;
            const char* srcL = cbl + (size_t)(c + 1) * NC * DD * 2;
            uint32_t bb = base + OFF_B + (uint32_t)((c + 1) & 1) * 16384u;
            #pragma unroll
            for (int i = tid; i < 1024; i += NTH) {
                int hf = i >> 9, idx = i & 511;
                const char* s = (hf ? srcL : srcH) + (size_t)idx * 16;
                uint32_t d = bb + (uint32_t)hf * 8192u + SW128((uint32_t)(idx * 16));
                CP_ASYNC16(d, s);
            }
            CP_COMMIT;
            CP_WAIT(1);
        } else {
            CP_WAIT(0);
        }
        __syncthreads();

        const uint32_t bufB = base + OFF_B + (uint32_t)(c & 1) * 16384u;

        float acc[4][4][4];
        #pragma unroll
        for (int mt = 0; mt < 4; ++mt)
            #pragma unroll
            for (int ntl = 0; ntl < 4; ++ntl)
                #pragma unroll
                for (int f = 0; f < 4; ++f) acc[mt][ntl][f] = 0.f;

        #pragma unroll
        for (int ks = 0; ks < 4; ++ks) {
            const uint32_t kcol = (uint32_t)(ks * 2);
            uint32_t bh[4][2], bl[4][2];
            #pragma unroll
            for (int np = 0; np < 2; ++np) {
                uint32_t co = ((kcol + bCs) ^ bSh[np]) << 4;
                LDMX4(bh[np * 2][0], bh[np * 2][1], bh[np * 2 + 1][0], bh[np * 2 + 1][1],
                      bufB + bRo[np] + co);
                LDMX4(bl[np * 2][0], bl[np * 2][1], bl[np * 2 + 1][0], bl[np * 2 + 1][1],
                      bufB + 8192u + bRo[np] + co);
            }
            uint32_t af[4][4];
            #pragma unroll
            for (int mt = 0; mt < 4; ++mt) {
                uint32_t addr = aB[mt] + (((kcol + aCs) ^ aS[mt]) << 4);
                LDMX4(af[mt][0], af[mt][1], af[mt][2], af[mt][3], addr);
            }
            // pass 1: xh * e_hi
            #pragma unroll
            for (int mt = 0; mt < 4; ++mt)
                #pragma unroll
                for (int ntl = 0; ntl < 4; ++ntl)
                    MMA16816(acc[mt][ntl][0], acc[mt][ntl][1], acc[mt][ntl][2], acc[mt][ntl][3],
                             af[mt][0], af[mt][1], af[mt][2], af[mt][3],
                             bh[ntl][0], bh[ntl][1]);
            // pass 2: xh * e_lo  (=> dot ~= xh . e, error = 2|xl.e| bounded by margin)
            #pragma unroll
            for (int mt = 0; mt < 4; ++mt)
                #pragma unroll
                for (int ntl = 0; ntl < 4; ++ntl)
                    MMA16816(acc[mt][ntl][0], acc[mt][ntl][1], acc[mt][ntl][2], acc[mt][ntl][3],
                             af[mt][0], af[mt][1], af[mt][2], af[mt][3],
                             bl[ntl][0], bl[ntl][1]);
        }

        // ---- argmin epilogue: dist' = e2 - 2*dot ----
        #pragma unroll
        for (int ntl = 0; ntl < 4; ++ntl) {
            int k = c * NC + n0 + 8 * ntl + 2 * t4;
            float2 e2p = *(const float2*)&e2s[k];
            #pragma unroll
            for (int mt = 0; mt < 4; ++mt) {
                float d00 = fmaf(acc[mt][ntl][0], -2.f, e2p.x);
                float d01 = fmaf(acc[mt][ntl][1], -2.f, e2p.y);
                float d10 = fmaf(acc[mt][ntl][2], -2.f, e2p.x);
                float d11 = fmaf(acc[mt][ntl][3], -2.f, e2p.y);
                int r0 = mt * 2, r1 = mt * 2 + 1;
                m2[r0] = fminf(m2[r0], fmaxf(d00, m1[r0]));
                i1[r0] = (d00 < m1[r0]) ? k : i1[r0];
                m1[r0] = fminf(m1[r0], d00);
                m2[r0] = fminf(m2[r0], fmaxf(d01, m1[r0]));
                i1[r0] = (d01 < m1[r0]) ? (k + 1) : i1[r0];
                m1[r0] = fminf(m1[r0], d01);
                m2[r1] = fminf(m2[r1], fmaxf(d10, m1[r1]));
                i1[r1] = (d10 < m1[r1]) ? k : i1[r1];
                m1[r1] = fminf(m1[r1], d10);
                m2[r1] = fminf(m2[r1], fmaxf(d11, m1[r1]));
                i1[r1] = (d11 < m1[r1]) ? (k + 1) : i1[r1];
                m1[r1] = fminf(m1[r1], d11);
            }
        }
    }

    // ---- quad reduce ----
    #pragma unroll
    for (int r = 0; r < 8; ++r) {
        #pragma unroll
        for (int o = 1; o <= 2; o <<= 1) {
            float om1 = __shfl_xor_sync(0xffffffffu, m1[r], o);
            float om2 = __shfl_xor_sync(0xffffffffu, m2[r], o);
            int   oi  = __shfl_xor_sync(0xffffffffu, i1[r], o);
            if (om1 < m1[r] || (om1 == m1[r] && oi < i1[r])) {
                m2[r] = fminf(m1[r], om2); m1[r] = om1; i1[r] = oi;
            } else {
                m2[r] = fminf(m2[r], om1);
            }
        }
    }

    // ---- stage per-code-half partials, merge across halves ----
    if (t4 == 0) {
        #pragma unroll
        for (int mt = 0; mt < 4; ++mt)
            #pragma unroll
            for (int h = 0; h < 2; ++h) {
                int r = mt * 2 + h;
                int tok = m0 + 16 * mt + 8 * h + gq;
                p1v[half * TT + tok] = m1[r];
                p1i[half * TT + tok] = i1[r];
                p2v[half * TT + tok] = m2[r];
            }
    }
    __syncthreads();

    const float se2max = sqrtf(__uint_as_float(g_e2max[g]));
    {
        float av = p1v[tid], a2 = p2v[tid]; int ai = p1i[tid];
        float bv = p1v[TT + tid], b2 = p2v[TT + tid]; int bi = p1i[TT + tid];
        float mm1, mm2; int ii1;
        if (bv < av || (bv == av && bi < ai)) { mm1 = bv; ii1 = bi; mm2 = fminf(av, b2); }
        else                                   { mm1 = av; ii1 = ai; mm2 = fminf(bv, a2); }
        bix[tid] = ii1;
        // provable bound: |dist_est - dist_exact| <= 2*||xl||*||e_k|| <= 2*||xl||*se2max
        float margin = 2.2f * sqrtf(xl2s[tid]) * se2max + 0.02f;
        if (tid < nt && (mm2 - mm1) <= margin) {
            int s = atomicAdd(&flg[0], 1);
            flg[1 + s] = tid;
        }
    }
    __syncthreads();

    // ---- exact fp32 fallback: mirrors reference arithmetic (x2 - 2*dot) + e2 ----
    {
        int cnt = flg[0];
        const float* cbg = cbf + (size_t)g * KK * DD;
        float* xscr = p1v + wid * 64;
        for (int f = wid; f < cnt; f += 4) {
            int t = flg[1 + f];
            xscr[lane]      = __ldg(xb + (size_t)lane * TS + t);
            xscr[lane + 32] = __ldg(xb + (size_t)(lane + 32) * TS + t);
            __syncwarp();
            float x2 = x2s[t];
            float bv = INF; int bi = 0;
            for (int q = 0; q < KK / 32; ++q) {
                int k = q * 32 + lane;
                const float* row = cbg + (size_t)k * DD;
                float dot = 0.f;
                #pragma unroll
                for (int d = 0; d < DD; ++d)
                    dot = fmaf(xscr[d], __ldg(row + d), dot);
                float dist = (x2 - 2.0f * dot) + e2s[k];
                if (dist < bv) { bv = dist; bi = k; }
            }
            #pragma unroll
            for (int o = 16; o > 0; o >>= 1) {
                float ov = __shfl_xor_sync(0xffffffffu, bv, o);
                int oi = __shfl_xor_sync(0xffffffffu, bi, o);
                if (ov < bv || (ov == bv && oi < bi)) { bv = ov; bi = oi; }
            }
            if (lane == 0) bix[t] = bi;
            __syncwarp();
        }
    }
    __syncthreads();

    // ---- gather winners (transpose-stage through B region) ----
    const float* cbg = cbf + (size_t)g * KK * DD;
    {
        const float* row = cbg + (size_t)bix[tid] * DD;
        #pragma unroll
        for (int q = 0; q < DD / 4; ++q) {
            float4 v = __ldg((const float4*)row + q);
            stg[(q * 4 + 0) * TT + tid] = v.x;
            stg[(q * 4 + 1) * TT + tid] = v.y;
            stg[(q * 4 + 2) * TT + tid] = v.z;
            stg[(q * 4 + 3) * TT + tid] = v.w;
        }
    }
    __syncthreads();

    // ---- coalesced writes (both output copies) ----
    float* out2 = out + (size_t)BB * CF * TS;
    const size_t obase = ((size_t)(b * CF + g * DD)) * TS + t0;
    if (nt == TT) {
        #pragma unroll
        for (int i = tid; i < DD * (TT / 4); i += NTH) {
            int dd = i >> 5, tq = i & 31;
            float4 v = *(const float4*)&stg[dd * TT + tq * 4];
            size_t o = obase + (size_t)dd * TS + tq * 4;
            *(float4*)(out + o) = v;
            if (two_copies) *(float4*)(out2 + o) = v;
        }
    } else {
        for (int i = tid; i < DD * TT; i += NTH) {
            int dd = i / TT, tt = i % TT;
            if (tt < nt) {
                float v = stg[dd * TT + tt];
                size_t o = obase + (size_t)dd * TS + tt;
                out[o] = v;
                if (two_copies) out2[o] = v;
            }
        }
    }
}

extern "C" void kernel_launch(void* const* d_in, const int* in_sizes, int n_in,
                              void* d_out, int out_size) {
    const float* x  = (const float*)d_in[0];
    const float* cb = (const float*)d_in[1];
    if (n_in >= 2 && in_sizes[0] == GG * KK * DD) {
        x = (const float*)d_in[1];
        cb = (const float*)d_in[0];
    }
    float* out = (float*)d_out;
    int two = (out_size >= 2 * BB * CF * TS) ? 1 : 0;

    cudaFuncSetAttribute(vq_main, cudaFuncAttributeMaxDynamicSharedMemorySize, SMEM_BYTES);

    prep_kernel<<<(GG * KK + PTH - 1) / PTH, PTH>>>(cb);
    vq_main<<<GG * BB * 32, NTH, SMEM_BYTES>>>(x, cb, out, two);
}

// round 10
// speedup vs baseline: 13.2803x; 13.2803x over previous
#include <cuda_runtime.h>
#include <cuda_bf16.h>
#include <cstdint>

#define GG   8
#define KK   1024
#define DD   64
#define BB   16
#define TS   4000
#define CF   512
#define TT   128        // tokens per CTA
#define NC   64         // codes per chunk
#define NCH  16
#define NTH  128
#define PTH  256

// ---------------- device globals ----------------
__device__ float g_e2[GG * KK];
__device__ unsigned int g_e2max[GG];
__device__ __align__(16) __nv_bfloat16 g_cbh[GG * KK * DD];
__device__ __align__(16) __nv_bfloat16 g_cbl[GG * KK * DD];
__device__ float g_cbT[GG * DD * KK];   // transposed fp32 codebook [g][d][k]

// ---------------- smem layout (bytes) ----------------
#define OFF_AH    0        // 16384: A hi bf16 SW128 (128 rows x 128B)
#define OFF_B     16384    // 32768: x stage / 2 B bufs (hi 8K + lo 8K each) / gather stage
#define OFF_E2S   49152    // 4096
#define OFF_X2S   53248    // 512  exact ||x||^2 per token
#define OFF_XL2   53760    // 512  ||x - xh||^2 per token
#define OFF_BIX   54272    // 512
#define OFF_PK1   54784    // 1024: [2][128] u32 key1 (reused as fallback x scratch)
#define OFF_PK2   55808    // 1024
#define OFF_PK3   56832    // 1024
#define OFF_FLG   57856    // 520
#define SMEM_BYTES 58376

#define SW128(o) ((o) ^ (((o) >> 3) & 0x70))

__device__ __forceinline__ uint32_t smem_u32(const void* p) {
    uint32_t a;
    asm("{ .reg .u64 t; cvta.to.shared.u64 t, %1; cvt.u32.u64 %0, t; }" : "=r"(a) : "l"(p));
    return a;
}

#define LDMX4(r0, r1, r2, r3, a) \
    asm volatile("ldmatrix.sync.aligned.m8n8.x4.shared.b16 {%0,%1,%2,%3}, [%4];" \
        : "=r"(r0), "=r"(r1), "=r"(r2), "=r"(r3) : "r"(a))

#define MMA16816(c0, c1, c2, c3, a0, a1, a2, a3, b0, b1) \
    asm volatile("mma.sync.aligned.m16n8k16.row.col.f32.bf16.bf16.f32 " \
        "{%0,%1,%2,%3}, {%4,%5,%6,%7}, {%8,%9}, {%0,%1,%2,%3};" \
        : "+f"(c0), "+f"(c1), "+f"(c2), "+f"(c3) \
        : "r"(a0), "r"(a1), "r"(a2), "r"(a3), "r"(b0), "r"(b1))

#define CP_ASYNC16(dst, src) \
    asm volatile("cp.async.cg.shared.global [%0], [%1], 16;" :: "r"(dst), "l"(src) : "memory")
#define CP_COMMIT  asm volatile("cp.async.commit_group;" ::: "memory")
#define CP_WAIT(n) asm volatile("cp.async.wait_group %0;" :: "n"(n) : "memory")

// monotone float -> u32 (order preserving)
__device__ __forceinline__ uint32_t f2sort(float f) {
    uint32_t s = __float_as_uint(f);
    return s ^ ((uint32_t)((int32_t)s >> 31) | 0x80000000u);
}
// inverse on 10-bit-truncated keys (lower bound of original value)
__device__ __forceinline__ float sort2f(uint32_t key) {
    uint32_t u = key & 0xFFFFFC00u;
    uint32_t v = (u & 0x80000000u) ? (u ^ 0x80000000u) : ~u;
    return __uint_as_float(v);
}
// insert key into sorted triple (q1<=q2<=q3)
__device__ __forceinline__ void top3_insert(uint32_t& q1, uint32_t& q2, uint32_t& q3, uint32_t x) {
    uint32_t a = min(q1, x), b = max(q1, x);
    q1 = a;
    uint32_t c = min(q2, b), d = max(q2, b);
    q2 = c;
    q3 = min(q3, d);
}
// merge two sorted triples -> sorted triple of 3 smallest
__device__ __forceinline__ void top3_merge(uint32_t& m1, uint32_t& m2, uint32_t& m3,
                                           uint32_t b1, uint32_t b2, uint32_t b3) {
    uint32_t c1 = min(m1, b1), d1 = max(m1, b1);
    uint32_t c2 = min(m2, b2), d2 = max(m2, b2);
    uint32_t c3 = min(m3, b3);
    m1 = c1;
    m2 = min(d1, c2);
    m3 = min(min(max(d1, c2), d2), c3);
}

// ---------------- prep: bf16 split codebook + transposed fp32 + e2 + e2max ----------------
__global__ void prep_kernel(const float* __restrict__ cb) {
    int r = blockIdx.x * blockDim.x + threadIdx.x;
    if (r < GG * KK) {
        const float* row = cb + (size_t)r * DD;
        int gg = r / KK, kk = r % KK;
        float s = 0.f;
        #pragma unroll
        for (int d = 0; d < DD; ++d) {
            float v = row[d];
            s = fmaf(v, v, s);
            __nv_bfloat16 h = __float2bfloat16(v);
            g_cbh[(size_t)r * DD + d] = h;
            g_cbl[(size_t)r * DD + d] = __float2bfloat16(v - __bfloat162float(h));
            g_cbT[((size_t)gg * DD + d) * KK + kk] = v;
        }
        g_e2[r] = s;
        atomicMax(&g_e2max[gg], __float_as_uint(s));
    }
}

__global__ __launch_bounds__(NTH, 3)
void vq_main(const float* __restrict__ x, const float* __restrict__ cbf,
             float* __restrict__ out, int two_copies) {
    extern __shared__ char smem[];
    const uint32_t base = smem_u32(smem);
    float*    stg  = (float*)(smem + OFF_B);
    float*    e2s  = (float*)(smem + OFF_E2S);
    float*    x2s  = (float*)(smem + OFF_X2S);
    float*    xl2s = (float*)(smem + OFF_XL2);
    int*      bix  = (int*)  (smem + OFF_BIX);
    uint32_t* pk1  = (uint32_t*)(smem + OFF_PK1);
    uint32_t* pk2  = (uint32_t*)(smem + OFF_PK2);
    uint32_t* pk3  = (uint32_t*)(smem + OFF_PK3);
    int*      flg  = (int*)  (smem + OFF_FLG);

    const int tid = threadIdx.x;
    const int wid = tid >> 5;
    const int lane = tid & 31;

    const int tile = blockIdx.x & 31;
    const int b = (blockIdx.x >> 5) & 15;
    const int g = blockIdx.x >> 9;
    const int t0 = tile * TT;
    const int nt = min(TT, TS - t0);

    if (tid == 0) flg[0] = 0;

    // ---- stage x tile fp32 into the B region ([d][t], zero-padded) ----
    const float* xb = x + ((size_t)(b * CF + g * DD)) * TS + t0;
    if (nt == TT) {
        #pragma unroll
        for (int i = tid; i < DD * (TT / 4); i += NTH) {
            int dd = i >> 5, tq = i & 31;
            float4 v = *(const float4*)(xb + (size_t)dd * TS + tq * 4);
            *(float4*)&stg[dd * TT + tq * 4] = v;
        }
    } else {
        for (int i = tid; i < DD * TT; i += NTH) {
            int dd = i / TT, tt = i % TT;
            stg[dd * TT + tt] = (tt < nt) ? xb[(size_t)dd * TS + tt] : 0.f;
        }
    }
    for (int i = tid; i < KK; i += NTH) e2s[i] = g_e2[g * KK + i];
    __syncthreads();

    // ---- build A hi (SW128) + x2 + xl2; thread t = token t ----
    {
        float s = 0.f, sl = 0.f;
        #pragma unroll
        for (int q = 0; q < 8; ++q) {
            uint32_t hp[4];
            #pragma unroll
            for (int pr = 0; pr < 4; ++pr) {
                float v0 = stg[(q * 8 + pr * 2) * TT + tid];
                float v1 = stg[(q * 8 + pr * 2 + 1) * TT + tid];
                s = fmaf(v0, v0, s);
                s = fmaf(v1, v1, s);
                __nv_bfloat16 h0 = __float2bfloat16(v0), h1 = __float2bfloat16(v1);
                float l0 = v0 - __bfloat162float(h0);
                float l1 = v1 - __bfloat162float(h1);
                sl = fmaf(l0, l0, sl);
                sl = fmaf(l1, l1, sl);
                hp[pr] = ((uint32_t)__bfloat16_as_ushort(h1) << 16) | __bfloat16_as_ushort(h0);
            }
            uint32_t off = SW128((uint32_t)(tid * 128 + q * 16));
            asm volatile("st.shared.v4.b32 [%0], {%1,%2,%3,%4};"
                :: "r"(base + OFF_AH + off), "r"(hp[0]), "r"(hp[1]), "r"(hp[2]), "r"(hp[3]) : "memory");
        }
        x2s[tid] = s;
        xl2s[tid] = sl;
    }
    __syncthreads();

    // ---- warp tiling: 64 tokens x 32 codes per warp ----
    const int m0 = (wid >> 1) * 64;
    const int n0 = (wid & 1) * 32;
    const int half = wid & 1;
    const int gq = lane >> 2;
    const int t4 = lane & 3;

    const uint32_t aRow = (uint32_t)(m0 + (lane & 15));
    const uint32_t aCs = (uint32_t)(lane >> 4);
    const uint32_t bRowBase = (uint32_t)(n0 + (lane & 7) + ((lane >> 4) << 3));
    const uint32_t bCs = (uint32_t)((lane >> 3) & 1);

    uint32_t aB[4], aS[4];
    #pragma unroll
    for (int mt = 0; mt < 4; ++mt) {
        uint32_t r = aRow + 16u * mt;
        aB[mt] = base + OFF_AH + r * 128u;
        aS[mt] = r & 7u;
    }
    uint32_t bRo[2], bSh[2];
    #pragma unroll
    for (int np = 0; np < 2; ++np) {
        uint32_t r = bRowBase + 16u * np;
        bRo[np] = r * 128u;
        bSh[np] = r & 7u;
    }

    uint32_t q1[8], q2[8], q3[8];
    #pragma unroll
    for (int r = 0; r < 8; ++r) { q1[r] = 0xFFFFFFFFu; q2[r] = 0xFFFFFFFFu; q3[r] = 0xFFFFFFFFu; }

    const char* cbh = (const char*)(g_cbh + (size_t)g * KK * DD);
    const char* cbl = (const char*)(g_cbl + (size_t)g * KK * DD);

    // prefetch chunk 0
    {
        #pragma unroll
        for (int i = tid; i < 1024; i += NTH) {
            int hf = i >> 9, idx = i & 511;
            const char* s = (hf ? cbl : cbh) + (size_t)idx * 16;
            uint32_t d = base + OFF_B + (uint32_t)hf * 8192u + SW128((uint32_t)(idx * 16));
            CP_ASYNC16(d, s);
        }
        CP_COMMIT;
    }

    for (int c = 0; c < NCH; ++c) {
        __syncthreads();
        if (c + 1 < NCH) {
            const char* srcH = cbh + (size_t)(c + 1) * NC * DD * 2;
            const char* srcL = cbl + (size_t)(c + 1) * NC * DD * 2;
            uint32_t bb = base + OFF_B + (uint32_t)((c + 1) & 1) * 16384u;
            #pragma unroll
            for (int i = tid; i < 1024; i += NTH) {
                int hf = i >> 9, idx = i & 511;
                const char* s = (hf ? srcL : srcH) + (size_t)idx * 16;
                uint32_t d = bb + (uint32_t)hf * 8192u + SW128((uint32_t)(idx * 16));
                CP_ASYNC16(d, s);
            }
            CP_COMMIT;
            CP_WAIT(1);
        } else {
            CP_WAIT(0);
        }
        __syncthreads();

        const uint32_t bufB = base + OFF_B + (uint32_t)(c & 1) * 16384u;

        float acc[4][4][4];
        #pragma unroll
        for (int mt = 0; mt < 4; ++mt)
            #pragma unroll
            for (int ntl = 0; ntl < 4; ++ntl)
                #pragma unroll
                for (int f = 0; f < 4; ++f) acc[mt][ntl][f] = 0.f;

        #pragma unroll
        for (int ks = 0; ks < 4; ++ks) {
            const uint32_t kcol = (uint32_t)(ks * 2);
            uint32_t bh[4][2], bl[4][2];
            #pragma unroll
            for (int np = 0; np < 2; ++np) {
                uint32_t co = ((kcol + bCs) ^ bSh[np]) << 4;
                LDMX4(bh[np * 2][0], bh[np * 2][1], bh[np * 2 + 1][0], bh[np * 2 + 1][1],
                      bufB + bRo[np] + co);
                LDMX4(bl[np * 2][0], bl[np * 2][1], bl[np * 2 + 1][0], bl[np * 2 + 1][1],
                      bufB + 8192u + bRo[np] + co);
            }
            uint32_t af[4][4];
            #pragma unroll
            for (int mt = 0; mt < 4; ++mt) {
                uint32_t addr = aB[mt] + (((kcol + aCs) ^ aS[mt]) << 4);
                LDMX4(af[mt][0], af[mt][1], af[mt][2], af[mt][3], addr);
            }
            // pass 1: xh * e_hi
            #pragma unroll
            for (int mt = 0; mt < 4; ++mt)
                #pragma unroll
                for (int ntl = 0; ntl < 4; ++ntl)
                    MMA16816(acc[mt][ntl][0], acc[mt][ntl][1], acc[mt][ntl][2], acc[mt][ntl][3],
                             af[mt][0], af[mt][1], af[mt][2], af[mt][3],
                             bh[ntl][0], bh[ntl][1]);
            // pass 2: xh * e_lo  => dot ~= xh . e; per-code error 2|xl.e_k|
            #pragma unroll
            for (int mt = 0; mt < 4; ++mt)
                #pragma unroll
                for (int ntl = 0; ntl < 4; ++ntl)
                    MMA16816(acc[mt][ntl][0], acc[mt][ntl][1], acc[mt][ntl][2], acc[mt][ntl][3],
                             af[mt][0], af[mt][1], af[mt][2], af[mt][3],
                             bl[ntl][0], bl[ntl][1]);
        }

        // ---- top-3 key epilogue: dist' = e2 - 2*dot ----
        #pragma unroll
        for (int ntl = 0; ntl < 4; ++ntl) {
            uint32_t k = (uint32_t)(c * NC + n0 + 8 * ntl + 2 * t4);
            float2 e2p = *(const float2*)&e2s[k];
            #pragma unroll
            for (int mt = 0; mt < 4; ++mt) {
                float d00 = fmaf(acc[mt][ntl][0], -2.f, e2p.x);
                float d01 = fmaf(acc[mt][ntl][1], -2.f, e2p.y);
                float d10 = fmaf(acc[mt][ntl][2], -2.f, e2p.x);
                float d11 = fmaf(acc[mt][ntl][3], -2.f, e2p.y);
                int r0 = mt * 2, r1 = mt * 2 + 1;
                top3_insert(q1[r0], q2[r0], q3[r0], (f2sort(d00) & 0xFFFFFC00u) | k);
                top3_insert(q1[r0], q2[r0], q3[r0], (f2sort(d01) & 0xFFFFFC00u) | (k + 1));
                top3_insert(q1[r1], q2[r1], q3[r1], (f2sort(d10) & 0xFFFFFC00u) | k);
                top3_insert(q1[r1], q2[r1], q3[r1], (f2sort(d11) & 0xFFFFFC00u) | (k + 1));
            }
        }
    }

    // ---- quad reduce (lanes t4=0..3 share each row) ----
    #pragma unroll
    for (int r = 0; r < 8; ++r) {
        #pragma unroll
        for (int o = 1; o <= 2; o <<= 1) {
            uint32_t o1 = __shfl_xor_sync(0xffffffffu, q1[r], o);
            uint32_t o2 = __shfl_xor_sync(0xffffffffu, q2[r], o);
            uint32_t o3 = __shfl_xor_sync(0xffffffffu, q3[r], o);
            top3_merge(q1[r], q2[r], q3[r], o1, o2, o3);
        }
    }

    // ---- stage per-code-half triples ----
    if (t4 == 0) {
        #pragma unroll
        for (int mt = 0; mt < 4; ++mt)
            #pragma unroll
            for (int h = 0; h < 2; ++h) {
                int r = mt * 2 + h;
                int tok = m0 + 16 * mt + 8 * h + gq;
                pk1[half * TT + tok] = q1[r];
                pk2[half * TT + tok] = q2[r];
                pk3[half * TT + tok] = q3[r];
            }
    }
    __syncthreads();

    // ---- merge halves + 3-tier resolve ----
    const float se2max = sqrtf(__uint_as_float(g_e2max[g]));
    const float* cbg = cbf + (size_t)g * KK * DD;
    {
        uint32_t k1 = pk1[tid], k2 = pk2[tid], k3 = pk3[tid];
        top3_merge(k1, k2, k3, pk1[TT + tid], pk2[TT + tid], pk3[TT + tid]);
        int i1 = (int)(k1 & 1023u);
        int i2 = (int)(k2 & 1023u);
        float v1 = sort2f(k1), v2 = sort2f(k2), v3 = sort2f(k3);
        // per-code error bound M = 2*||xl||*max||e||; decision threshold 2M + slack
        float thr = 4.2f * sqrtf(xl2s[tid]) * se2max + 0.12f;
        int res = i1;
        if (tid < nt) {
            if (v2 - v1 > thr) {
                // provably unique winner
            } else if (v3 - v1 > thr) {
                // true argmin provably in {i1, i2}: exact fp32 compare (reference order)
                float x2 = x2s[tid];
                const float* r1 = cbg + (size_t)i1 * DD;
                const float* r2 = cbg + (size_t)i2 * DD;
                float dot1 = 0.f, dot2 = 0.f;
                #pragma unroll
                for (int d = 0; d < DD; ++d) {
                    float xv = __ldg(xb + (size_t)d * TS + tid);
                    dot1 = fmaf(xv, __ldg(r1 + d), dot1);
                    dot2 = fmaf(xv, __ldg(r2 + d), dot2);
                }
                float e1 = (x2 - 2.0f * dot1) + e2s[i1];
                float e2v = (x2 - 2.0f * dot2) + e2s[i2];
                if (e2v < e1 || (e2v == e1 && i2 < i1)) res = i2;
            } else {
                int s = atomicAdd(&flg[0], 1);
                flg[1 + s] = tid;
            }
        }
        bix[tid] = res;
    }
    __syncthreads();

    // ---- tier-3: full exact scan via transposed codebook (coalesced) ----
    {
        int cnt = flg[0];
        const float* ct = g_cbT + (size_t)g * DD * KK;
        float* xscr = (float*)pk1 + wid * 64;   // pk region dead now
        const float INF = __int_as_float(0x7f800000);
        for (int f = wid; f < cnt; f += 4) {
            int t = flg[1 + f];
            xscr[lane]      = __ldg(xb + (size_t)lane * TS + t);
            xscr[lane + 32] = __ldg(xb + (size_t)(lane + 32) * TS + t);
            __syncwarp();
            float x2 = x2s[t];
            float bv = INF; int bi = 0;
            for (int q = 0; q < KK / 32; ++q) {
                int k = q * 32 + lane;
                float dot = 0.f;
                #pragma unroll
                for (int d = 0; d < DD; ++d)
                    dot = fmaf(xscr[d], __ldg(ct + (size_t)d * KK + k), dot);
                float dist = (x2 - 2.0f * dot) + e2s[k];
                if (dist < bv) { bv = dist; bi = k; }
            }
            #pragma unroll
            for (int o = 16; o > 0; o >>= 1) {
                float ov = __shfl_xor_sync(0xffffffffu, bv, o);
                int oi = __shfl_xor_sync(0xffffffffu, bi, o);
                if (ov < bv || (ov == bv && oi < bi)) { bv = ov; bi = oi; }
            }
            if (lane == 0) bix[t] = bi;
            __syncwarp();
        }
    }
    __syncthreads();

    // ---- gather winners (transpose-stage through B region) ----
    {
        const float* row = cbg + (size_t)bix[tid] * DD;
        #pragma unroll
        for (int q = 0; q < DD / 4; ++q) {
            float4 v = __ldg((const float4*)row + q);
            stg[(q * 4 + 0) * TT + tid] = v.x;
            stg[(q * 4 + 1) * TT + tid] = v.y;
            stg[(q * 4 + 2) * TT + tid] = v.z;
            stg[(q * 4 + 3) * TT + tid] = v.w;
        }
    }
    __syncthreads();

    // ---- coalesced writes (both output copies) ----
    float* out2 = out + (size_t)BB * CF * TS;
    const size_t obase = ((size_t)(b * CF + g * DD)) * TS + t0;
    if (nt == TT) {
        #pragma unroll
        for (int i = tid; i < DD * (TT / 4); i += NTH) {
            int dd = i >> 5, tq = i & 31;
            float4 v = *(const float4*)&stg[dd * TT + tq * 4];
            size_t o = obase + (size_t)dd * TS + tq * 4;
            *(float4*)(out + o) = v;
            if (two_copies) *(float4*)(out2 + o) = v;
        }
    } else {
        for (int i = tid; i < DD * TT; i += NTH) {
            int dd = i / TT, tt = i % TT;
            if (tt < nt) {
                float v = stg[dd * TT + tt];
                size_t o = obase + (size_t)dd * TS + tt;
                out[o] = v;
                if (two_copies) out2[o] = v;
            }
        }
    }
}

extern "C" void kernel_launch(void* const* d_in, const int* in_sizes, int n_in,
                              void* d_out, int out_size) {
    const float* x  = (const float*)d_in[0];
    const float* cb = (const float*)d_in[1];
    if (n_in >= 2 && in_sizes[0] == GG * KK * DD) {
        x = (const float*)d_in[1];
        cb = (const float*)d_in[0];
    }
    float* out = (float*)d_out;
    int two = (out_size >= 2 * BB * CF * TS) ? 1 : 0;

    cudaFuncSetAttribute(vq_main, cudaFuncAttributeMaxDynamicSharedMemorySize, SMEM_BYTES);

    prep_kernel<<<(GG * KK + PTH - 1) / PTH, PTH>>>(cb);
    vq_main<<<GG * BB * 32, NTH, SMEM_BYTES>>>(x, cb, out, two);
}